// round 10
// baseline (speedup 1.0000x reference)
#include <cuda_runtime.h>
#include <cuda_fp16.h>
#include <math.h>
#include <stdint.h>

// ---------------- problem dims ----------------
#define B_DIM 64
#define T_DIM 2048
#define D_DIM 256
#define M_DIM (B_DIM * T_DIM)   // 131072
#define EPS 1e-7f
#define WSCALE 16.0f
#define WSCALE_INV 0.0625f

// ---------------- GEMM tiling ----------------
#define BM 64
#define BK 32
#define NIT (D_DIM / BK)        // 8 k-chunks
#define NSTAGE 4
#define SA_B 80                 // smem row stride bytes (32 halves + 16B pad)

#define A_BYTES (BM * SA_B)                  // 5120
#define STAGE_BYTES (A_BYTES + 256 * SA_B)   // 25600
#define A_OFF(s) ((s) * STAGE_BYTES)
#define B_OFF(s) ((s) * STAGE_BYTES + A_BYTES)
#define SMEM_TOTAL (NSTAGE * STAGE_BYTES)    // 102400

// ---------------- scratch globals ----------------
__device__ float g_scores[M_DIM];
__device__ float g_weights[M_DIM];
__device__ __align__(16) __half g_Wt[D_DIM * D_DIM];   // [n][k], W*16 fp16

// ---------------- helpers ----------------
__device__ __forceinline__ uint32_t smem_u32(const void* p) {
    uint32_t a;
    asm("{ .reg .u64 t; cvta.to.shared.u64 t, %1; cvt.u32.u64 %0, t; }"
        : "=r"(a) : "l"(p));
    return a;
}

__device__ __forceinline__ void mma16816(float* c, const uint32_t* a,
                                         uint32_t b0, uint32_t b1) {
    asm volatile(
        "mma.sync.aligned.m16n8k16.row.col.f32.f16.f16.f32 "
        "{%0,%1,%2,%3}, {%4,%5,%6,%7}, {%8,%9}, {%0,%1,%2,%3};\n"
        : "+f"(c[0]), "+f"(c[1]), "+f"(c[2]), "+f"(c[3])
        : "r"(a[0]), "r"(a[1]), "r"(a[2]), "r"(a[3]), "r"(b0), "r"(b1));
}

__device__ __forceinline__ void ldsm_x4(uint32_t* r, uint32_t addr) {
    asm volatile("ldmatrix.sync.aligned.m8n8.x4.shared.b16 {%0,%1,%2,%3}, [%4];"
        : "=r"(r[0]), "=r"(r[1]), "=r"(r[2]), "=r"(r[3]) : "r"(addr));
}

__device__ __forceinline__ void cp_async16(uint32_t dst, const void* src) {
    asm volatile("cp.async.cg.shared.global [%0], [%1], 16;"
                 :: "r"(dst), "l"(src));
}
#define CP_COMMIT() asm volatile("cp.async.commit_group;" ::: "memory")
#define CP_WAIT2()  asm volatile("cp.async.wait_group 2;" ::: "memory")

// ---------------------------------------------------------------------------
// Prep: zero d_out; transpose W*16 into fp16 [n][k]
// ---------------------------------------------------------------------------
__global__ void prep_kernel(const float* __restrict__ W, float* __restrict__ out) {
    int idx = blockIdx.x * blockDim.x + threadIdx.x;   // 0..65535
    if (idx < B_DIM * D_DIM) out[idx] = 0.0f;
    int k = idx >> 8;
    int n = idx & 255;
    g_Wt[n * D_DIM + k] = __float2half_rn(W[k * D_DIM + n] * WSCALE);
}

// ---------------------------------------------------------------------------
// GEMM + tanh + uw-dot: mma.sync f16 single-term, 4-stage pipeline,
// B via cp.async (3 chunks deep).  grid = M/64 = 2048, block = 256
// (8 warps: 2m x 4n), warp tile 32x64, 2 CTAs/SM.
// ---------------------------------------------------------------------------
__global__ __launch_bounds__(256, 2) void gemm_score_kernel(
    const float* __restrict__ x,      // [M, 256]
    const float* __restrict__ bias,   // [256]
    const float* __restrict__ uw,     // [256]
    float* __restrict__ scores)       // [M]
{
    extern __shared__ char smem[];
    __shared__ float red[BM];
    const uint32_t sb = smem_u32(smem);
    const int tid = threadIdx.x;
    const int wid = tid >> 5;
    const int lane = tid & 31;
    const int wm = wid >> 2;       // 0..1
    const int wn = wid & 3;        // 0..3
    const int gid = lane >> 2;     // 0..7
    const int tg = lane & 3;       // 0..3
    const int m0 = blockIdx.x * BM;

    float acc[2][8][4];
#pragma unroll
    for (int mt = 0; mt < 2; mt++)
#pragma unroll
        for (int nt = 0; nt < 8; nt++)
#pragma unroll
            for (int r = 0; r < 4; r++) acc[mt][nt][r] = 0.0f;

    // ---- load indexing ----
    const int ar = tid >> 2;             // x row 0..63
    const int ak8 = (tid & 3) * 8;       // x k-offset (8 floats)
    const int wr0 = tid >> 2;            // W base row (then +i*64)
    const int wq = tid & 3;              // W 16B slice index

    // ---- ldmatrix addressing ----
    const uint32_t a_lds = sb + (wm * 32 + (lane & 15)) * SA_B + (lane >> 4) * 16;
    const int brow = wn * 64 + (lane & 7) + ((lane >> 4) << 3);  // + p*16
    const int bkh = (lane >> 3) & 1;

    float4 pa0, pa1;

#define LDG_A(c)                                                              \
    do {                                                                      \
        int k0 = (c) * BK;                                                    \
        pa0 = *(const float4*)&x[(size_t)(m0 + ar) * D_DIM + k0 + ak8];       \
        pa1 = *(const float4*)&x[(size_t)(m0 + ar) * D_DIM + k0 + ak8 + 4];   \
    } while (0)

#define STS_A(s)                                                              \
    do {                                                                      \
        union { __half2 h[4]; uint4 u; } hh;                                  \
        hh.h[0] = __floats2half2_rn(pa0.x, pa0.y);                            \
        hh.h[1] = __floats2half2_rn(pa0.z, pa0.w);                            \
        hh.h[2] = __floats2half2_rn(pa1.x, pa1.y);                            \
        hh.h[3] = __floats2half2_rn(pa1.z, pa1.w);                            \
        *(uint4*)(smem + A_OFF(s) + ar * SA_B + ak8 * 2) = hh.u;              \
    } while (0)

#define CPB(c, s)                                                             \
    do {                                                                      \
        int k0 = (c) * BK;                                                    \
        _Pragma("unroll")                                                     \
        for (int i = 0; i < 4; i++) {                                         \
            int row = wr0 + i * 64;                                           \
            int q = wq ^ ((row >> 3) & 3);                                    \
            cp_async16(sb + B_OFF(s) + row * SA_B + q * 16,                   \
                       &g_Wt[row * D_DIM + k0 + wq * 8]);                     \
        }                                                                     \
    } while (0)

    // prologue: A0 staged, B0..B2 in flight (groups 0..2), A1 in regs
    LDG_A(0);
    STS_A(0);
    CPB(0, 0); CP_COMMIT();
    CPB(1, 1); CP_COMMIT();
    CPB(2, 2); CP_COMMIT();
    LDG_A(1);

    for (int c = 0; c < NIT; c++) {
        const int cur = c % NSTAGE;
        CP_WAIT2();                            // B of chunk c landed
        __syncthreads();                       // + A STS visible
        if (c + 1 < NIT) STS_A((c + 1) % NSTAGE);
        if (c + 3 < NIT) CPB(c + 3, (c + 3) % NSTAGE);
        if (c + 2 < NIT) LDG_A(c + 2);
        CP_COMMIT();                           // exactly one group per iter

        uint32_t a[2][2][4];
#pragma unroll
        for (int mt = 0; mt < 2; mt++)
#pragma unroll
            for (int ks = 0; ks < 2; ks++)
                ldsm_x4(a[mt][ks], a_lds + A_OFF(cur) + mt * 16 * SA_B + ks * 32);

#pragma unroll
        for (int p = 0; p < 4; p++) {
            int row = brow + p * 16;
            int x3 = (row >> 3) & 3;
            uint32_t baddr = sb + B_OFF(cur) + row * SA_B;
            uint32_t b0[4], b1[4];
            ldsm_x4(b0, baddr + ((bkh + 0) ^ x3) * 16);
            ldsm_x4(b1, baddr + ((bkh + 2) ^ x3) * 16);
#pragma unroll
            for (int mt = 0; mt < 2; mt++) {
                mma16816(acc[mt][2 * p],     a[mt][0], b0[0], b0[1]);
                mma16816(acc[mt][2 * p + 1], a[mt][0], b0[2], b0[3]);
                mma16816(acc[mt][2 * p],     a[mt][1], b1[0], b1[1]);
                mma16816(acc[mt][2 * p + 1], a[mt][1], b1[2], b1[3]);
            }
        }
    }

    // ---- epilogue: score(m) = sum_n tanh(acc/16 + b[n]) * uw[n] ----
    if (tid < BM) red[tid] = 0.0f;
    __syncthreads();

    float rowsum[4] = {0.f, 0.f, 0.f, 0.f};
#pragma unroll
    for (int nt = 0; nt < 8; nt++) {
        int c0 = wn * 64 + nt * 8 + tg * 2;
        float u0 = __ldg(&uw[c0]), u1 = __ldg(&uw[c0 + 1]);
        float b0 = __ldg(&bias[c0]), b1 = __ldg(&bias[c0 + 1]);
#pragma unroll
        for (int mt = 0; mt < 2; mt++) {
            rowsum[mt * 2 + 0] += tanhf(fmaf(acc[mt][nt][0], WSCALE_INV, b0)) * u0
                                + tanhf(fmaf(acc[mt][nt][1], WSCALE_INV, b1)) * u1;
            rowsum[mt * 2 + 1] += tanhf(fmaf(acc[mt][nt][2], WSCALE_INV, b0)) * u0
                                + tanhf(fmaf(acc[mt][nt][3], WSCALE_INV, b1)) * u1;
        }
    }
#pragma unroll
    for (int i = 0; i < 4; i++) {
        rowsum[i] += __shfl_xor_sync(0xffffffffu, rowsum[i], 1);
        rowsum[i] += __shfl_xor_sync(0xffffffffu, rowsum[i], 2);
    }
    if (tg == 0) {
        atomicAdd(&red[wm * 32 + gid], rowsum[0]);
        atomicAdd(&red[wm * 32 + gid + 8], rowsum[1]);
        atomicAdd(&red[wm * 32 + 16 + gid], rowsum[2]);
        atomicAdd(&red[wm * 32 + 16 + gid + 8], rowsum[3]);
    }
    __syncthreads();
    if (tid < BM) scores[m0 + tid] = red[tid];
}

// ---------------------------------------------------------------------------
// Softmax over T per batch (reference semantics: raw exp, *mask, +EPS)
// ---------------------------------------------------------------------------
__global__ __launch_bounds__(256) void softmax_kernel(
    const float* __restrict__ scores,
    const int* __restrict__ mask,
    float* __restrict__ weights)
{
    __shared__ float sm[256];
    const int b = blockIdx.x;
    const int tid = threadIdx.x;
    const size_t base = (size_t)b * T_DIM;

    float e[T_DIM / 256];
    float s = 0.0f;
#pragma unroll
    for (int i = 0; i < T_DIM / 256; i++) {
        int t = i * 256 + tid;
        float v = expf(scores[base + t]) * (float)mask[base + t];
        e[i] = v;
        s += v;
    }
    sm[tid] = s;
    __syncthreads();
    for (int off = 128; off > 0; off >>= 1) {
        if (tid < off) sm[tid] += sm[tid + off];
        __syncthreads();
    }
    float inv = 1.0f / (sm[0] + EPS);
#pragma unroll
    for (int i = 0; i < T_DIM / 256; i++) {
        int t = i * 256 + tid;
        weights[base + t] = e[i] * inv;
    }
}

// ---------------------------------------------------------------------------
// out[b,d] = sum_t a[b,t] * x[b,t,d] — 4-deep batching, 4 CTAs/SM
// grid = (T/128, B), block 256: 4 t-groups x 64 d-float4, 32 t each
// ---------------------------------------------------------------------------
__global__ __launch_bounds__(256, 4) void wsum_kernel(
    const float* __restrict__ x,
    const float* __restrict__ weights,
    float* __restrict__ out)
{
    const int b = blockIdx.y;
    const int tbase = blockIdx.x * 128;
    const int d4 = (threadIdx.x & 63);
    const int tgrp = threadIdx.x >> 6;

    const float4* xb = (const float4*)(x + ((size_t)b * T_DIM + tbase + tgrp * 32) * D_DIM) + d4;
    const float* wb = weights + (size_t)b * T_DIM + tbase + tgrp * 32;

    float4 acc = make_float4(0.f, 0.f, 0.f, 0.f);
#pragma unroll
    for (int i = 0; i < 32; i += 4) {
        float w0 = __ldg(&wb[i + 0]);
        float w1 = __ldg(&wb[i + 1]);
        float w2 = __ldg(&wb[i + 2]);
        float w3 = __ldg(&wb[i + 3]);
        float4 v0 = xb[(size_t)(i + 0) * (D_DIM / 4)];
        float4 v1 = xb[(size_t)(i + 1) * (D_DIM / 4)];
        float4 v2 = xb[(size_t)(i + 2) * (D_DIM / 4)];
        float4 v3 = xb[(size_t)(i + 3) * (D_DIM / 4)];
        acc.x = fmaf(w0, v0.x, acc.x); acc.y = fmaf(w0, v0.y, acc.y);
        acc.z = fmaf(w0, v0.z, acc.z); acc.w = fmaf(w0, v0.w, acc.w);
        acc.x = fmaf(w1, v1.x, acc.x); acc.y = fmaf(w1, v1.y, acc.y);
        acc.z = fmaf(w1, v1.z, acc.z); acc.w = fmaf(w1, v1.w, acc.w);
        acc.x = fmaf(w2, v2.x, acc.x); acc.y = fmaf(w2, v2.y, acc.y);
        acc.z = fmaf(w2, v2.z, acc.z); acc.w = fmaf(w2, v2.w, acc.w);
        acc.x = fmaf(w3, v3.x, acc.x); acc.y = fmaf(w3, v3.y, acc.y);
        acc.z = fmaf(w3, v3.z, acc.z); acc.w = fmaf(w3, v3.w, acc.w);
    }
    float* o = out + b * D_DIM + d4 * 4;
    atomicAdd(o + 0, acc.x);
    atomicAdd(o + 1, acc.y);
    atomicAdd(o + 2, acc.z);
    atomicAdd(o + 3, acc.w);
}

// ---------------------------------------------------------------------------
extern "C" void kernel_launch(void* const* d_in, const int* in_sizes, int n_in,
                              void* d_out, int out_size) {
    const float* x    = (const float*)d_in[0];
    const float* W    = (const float*)d_in[1];
    const float* bias = (const float*)d_in[2];
    const float* uw   = (const float*)d_in[3];
    const int*   mask = (const int*)d_in[4];
    float* out = (float*)d_out;

    float* scores;
    float* weights;
    cudaGetSymbolAddress((void**)&scores, g_scores);
    cudaGetSymbolAddress((void**)&weights, g_weights);

    cudaFuncSetAttribute(gemm_score_kernel,
                         cudaFuncAttributeMaxDynamicSharedMemorySize, SMEM_TOTAL);

    prep_kernel<<<256, 256>>>(W, out);

    gemm_score_kernel<<<M_DIM / BM, 256, SMEM_TOTAL>>>(x, bias, uw, scores);

    softmax_kernel<<<B_DIM, 256>>>(scores, mask, weights);

    dim3 g3(T_DIM / 128, B_DIM);
    wsum_kernel<<<g3, 256>>>(x, weights, out);
}

// round 11
// speedup vs baseline: 1.1034x; 1.1034x over previous
#include <cuda_runtime.h>
#include <cuda_fp16.h>
#include <math.h>
#include <stdint.h>

// ---------------- problem dims ----------------
#define B_DIM 64
#define T_DIM 2048
#define D_DIM 256
#define M_DIM (B_DIM * T_DIM)   // 131072
#define EPS 1e-7f
#define WSCALE 16.0f
#define WSCALE_INV 0.0625f

// ---------------- GEMM tiling ----------------
#define BM 64
#define BK 32
#define NIT (D_DIM / BK)        // 8 k-chunks
#define NSTAGE_B 3
#define SA_B 80                 // smem row stride bytes (32 halves + 16B pad)

#define A_CH_BYTES (BM * SA_B)               // 5120 per k-chunk
#define A_TOTAL (NIT * A_CH_BYTES)           // 40960 (persistent)
#define B_ST_BYTES (256 * SA_B)              // 20480 per stage
#define A_CH(c) ((c) * A_CH_BYTES)
#define B_ST(s) (A_TOTAL + (s) * B_ST_BYTES)
#define SMEM_TOTAL (A_TOTAL + NSTAGE_B * B_ST_BYTES)   // 102400

// ---------------- scratch globals ----------------
__device__ float g_U[B_DIM * D_DIM];   // unnormalized output
__device__ float g_S[B_DIM];           // exp sums
__device__ __align__(16) __half g_Wt[D_DIM * D_DIM];   // [n][k], W*16 fp16

// ---------------- helpers ----------------
__device__ __forceinline__ uint32_t smem_u32(const void* p) {
    uint32_t a;
    asm("{ .reg .u64 t; cvta.to.shared.u64 t, %1; cvt.u32.u64 %0, t; }"
        : "=r"(a) : "l"(p));
    return a;
}

__device__ __forceinline__ void mma16816(float* c, const uint32_t* a,
                                         uint32_t b0, uint32_t b1) {
    asm volatile(
        "mma.sync.aligned.m16n8k16.row.col.f32.f16.f16.f32 "
        "{%0,%1,%2,%3}, {%4,%5,%6,%7}, {%8,%9}, {%0,%1,%2,%3};\n"
        : "+f"(c[0]), "+f"(c[1]), "+f"(c[2]), "+f"(c[3])
        : "r"(a[0]), "r"(a[1]), "r"(a[2]), "r"(a[3]), "r"(b0), "r"(b1));
}

__device__ __forceinline__ void ldsm_x4(uint32_t* r, uint32_t addr) {
    asm volatile("ldmatrix.sync.aligned.m8n8.x4.shared.b16 {%0,%1,%2,%3}, [%4];"
        : "=r"(r[0]), "=r"(r[1]), "=r"(r[2]), "=r"(r[3]) : "r"(addr));
}

__device__ __forceinline__ void cp_async16(uint32_t dst, const void* src) {
    asm volatile("cp.async.cg.shared.global [%0], [%1], 16;"
                 :: "r"(dst), "l"(src));
}
#define CP_COMMIT() asm volatile("cp.async.commit_group;" ::: "memory")
#define CP_WAIT1()  asm volatile("cp.async.wait_group 1;" ::: "memory")

// ---------------------------------------------------------------------------
// Prep: zero g_U/g_S; transpose W*16 into fp16 [n][k]
// ---------------------------------------------------------------------------
__global__ void prep_kernel(const float* __restrict__ W) {
    int idx = blockIdx.x * blockDim.x + threadIdx.x;   // 0..65535
    if (idx < B_DIM * D_DIM) g_U[idx] = 0.0f;
    if (idx < B_DIM) g_S[idx] = 0.0f;
    int k = idx >> 8;
    int n = idx & 255;
    g_Wt[n * D_DIM + k] = __float2half_rn(W[k * D_DIM + n] * WSCALE);
}

// ---------------------------------------------------------------------------
// Fused GEMM + tanh + uw-dot + exp + weighted-sum partials.
// grid = M/64 = 2048, block = 256 (8 warps: 2m x 4n), warp tile 32x64.
// A persistent in smem (fp16), B via 3-stage cp.async ring. 2 CTAs/SM.
// ---------------------------------------------------------------------------
__global__ __launch_bounds__(256, 2) void gemm_fused_kernel(
    const float* __restrict__ x,      // [M, 256]
    const float* __restrict__ bias,   // [256]
    const float* __restrict__ uw,     // [256]
    const int*   __restrict__ mask)   // [M]
{
    extern __shared__ char smem[];
    __shared__ float red[BM];
    __shared__ float sm_e[BM];
    const uint32_t sb = smem_u32(smem);
    const int tid = threadIdx.x;
    const int wid = tid >> 5;
    const int lane = tid & 31;
    const int wm = wid >> 2;       // 0..1
    const int wn = wid & 3;        // 0..3
    const int gid = lane >> 2;     // 0..7
    const int tg = lane & 3;       // 0..3
    const int m0 = blockIdx.x * BM;

    float acc[2][8][4];
#pragma unroll
    for (int mt = 0; mt < 2; mt++)
#pragma unroll
        for (int nt = 0; nt < 8; nt++)
#pragma unroll
            for (int r = 0; r < 4; r++) acc[mt][nt][r] = 0.0f;

    // ---- load indexing ----
    const int ar = tid >> 2;             // x row 0..63
    const int ak8 = (tid & 3) * 8;       // x k-offset within chunk (8 floats)
    const int wr0 = tid >> 2;            // W base row (then +i*64)
    const int wq = tid & 3;              // W 16B slice index

    // ---- ldmatrix addressing ----
    const uint32_t a_lds = sb + (wm * 32 + (lane & 15)) * SA_B + (lane >> 4) * 16;
    const int brow = wn * 64 + (lane & 7) + ((lane >> 4) << 3);  // + p*16
    const int bkh = (lane >> 3) & 1;

#define CPB(c, s)                                                             \
    do {                                                                      \
        int k0 = (c) * BK;                                                    \
        _Pragma("unroll")                                                     \
        for (int i = 0; i < 4; i++) {                                         \
            int row = wr0 + i * 64;                                           \
            int q = wq ^ ((row >> 3) & 3);                                    \
            cp_async16(sb + B_ST(s) + row * SA_B + q * 16,                    \
                       &g_Wt[row * D_DIM + k0 + wq * 8]);                     \
        }                                                                     \
    } while (0)

    // prologue: B0/B1 in flight first, then persistent A load (overlaps)
    CPB(0, 0); CP_COMMIT();
    CPB(1, 1); CP_COMMIT();
#pragma unroll
    for (int c = 0; c < NIT; c++) {
        int k0 = c * BK;
        float4 pa0 = *(const float4*)&x[(size_t)(m0 + ar) * D_DIM + k0 + ak8];
        float4 pa1 = *(const float4*)&x[(size_t)(m0 + ar) * D_DIM + k0 + ak8 + 4];
        union { __half2 h[4]; uint4 u; } hh;
        hh.h[0] = __floats2half2_rn(pa0.x, pa0.y);
        hh.h[1] = __floats2half2_rn(pa0.z, pa0.w);
        hh.h[2] = __floats2half2_rn(pa1.x, pa1.y);
        hh.h[3] = __floats2half2_rn(pa1.z, pa1.w);
        *(uint4*)(smem + A_CH(c) + ar * SA_B + ak8 * 2) = hh.u;
    }

    for (int c = 0; c < NIT; c++) {
        const int cur = c % NSTAGE_B;
        CP_WAIT1();                            // B of chunk c landed
        __syncthreads();                       // all threads' stores visible
        if (c + 2 < NIT) CPB(c + 2, (c + 2) % NSTAGE_B);
        CP_COMMIT();                           // exactly one group per iter

        uint32_t a[2][2][4];
#pragma unroll
        for (int mt = 0; mt < 2; mt++)
#pragma unroll
            for (int ks = 0; ks < 2; ks++)
                ldsm_x4(a[mt][ks], a_lds + A_CH(c) + mt * 16 * SA_B + ks * 32);

#pragma unroll
        for (int p = 0; p < 4; p++) {
            int row = brow + p * 16;
            int x3 = (row >> 3) & 3;
            uint32_t baddr = sb + B_ST(cur) + row * SA_B;
            uint32_t b0[4], b1[4];
            ldsm_x4(b0, baddr + ((bkh + 0) ^ x3) * 16);
            ldsm_x4(b1, baddr + ((bkh + 2) ^ x3) * 16);
#pragma unroll
            for (int mt = 0; mt < 2; mt++) {
                mma16816(acc[mt][2 * p],     a[mt][0], b0[0], b0[1]);
                mma16816(acc[mt][2 * p + 1], a[mt][0], b0[2], b0[3]);
                mma16816(acc[mt][2 * p],     a[mt][1], b1[0], b1[1]);
                mma16816(acc[mt][2 * p + 1], a[mt][1], b1[2], b1[3]);
            }
        }
    }

    // ---- epilogue 1: score(m) = sum_n tanh(acc/16 + b[n]) * uw[n] ----
    if (tid < BM) red[tid] = 0.0f;
    __syncthreads();

    float rowsum[4] = {0.f, 0.f, 0.f, 0.f};
#pragma unroll
    for (int nt = 0; nt < 8; nt++) {
        int c0 = wn * 64 + nt * 8 + tg * 2;
        float u0 = __ldg(&uw[c0]), u1 = __ldg(&uw[c0 + 1]);
        float b0 = __ldg(&bias[c0]), b1 = __ldg(&bias[c0 + 1]);
#pragma unroll
        for (int mt = 0; mt < 2; mt++) {
            rowsum[mt * 2 + 0] += tanhf(fmaf(acc[mt][nt][0], WSCALE_INV, b0)) * u0
                                + tanhf(fmaf(acc[mt][nt][1], WSCALE_INV, b1)) * u1;
            rowsum[mt * 2 + 1] += tanhf(fmaf(acc[mt][nt][2], WSCALE_INV, b0)) * u0
                                + tanhf(fmaf(acc[mt][nt][3], WSCALE_INV, b1)) * u1;
        }
    }
#pragma unroll
    for (int i = 0; i < 4; i++) {
        rowsum[i] += __shfl_xor_sync(0xffffffffu, rowsum[i], 1);
        rowsum[i] += __shfl_xor_sync(0xffffffffu, rowsum[i], 2);
    }
    if (tg == 0) {
        atomicAdd(&red[wm * 32 + gid], rowsum[0]);
        atomicAdd(&red[wm * 32 + gid + 8], rowsum[1]);
        atomicAdd(&red[wm * 32 + 16 + gid], rowsum[2]);
        atomicAdd(&red[wm * 32 + 16 + gid + 8], rowsum[3]);
    }
    __syncthreads();

    // ---- epilogue 2: e_t, S partial, U partial from persistent fp16 A ----
    const int b = m0 >> 11;   // 2048 rows per batch
    if (tid < BM) {
        float e = expf(red[tid]) * (float)mask[m0 + tid];
        sm_e[tid] = e;
#pragma unroll
        for (int off = 16; off > 0; off >>= 1)
            e += __shfl_xor_sync(0xffffffffu, e, off);
        if ((tid & 31) == 0) atomicAdd(&g_S[b], e);
    }
    __syncthreads();

    {
        const int d = tid;               // 0..255
        const int ch = d >> 5;           // k-chunk
        const int kk = d & 31;           // k within chunk
        const __half* col = (const __half*)(smem + A_CH(ch) + kk * 2);
        float u = 0.0f;
#pragma unroll 8
        for (int t = 0; t < BM; t++)
            u = fmaf(sm_e[t], __half2float(col[t * (SA_B / 2)]), u);
        atomicAdd(&g_U[b * D_DIM + d], u);
    }
}

// ---------------------------------------------------------------------------
// Normalize: out[b,d] = U[b,d] / (S[b] + EPS)
// ---------------------------------------------------------------------------
__global__ void norm_kernel(float* __restrict__ out) {
    int i = blockIdx.x * blockDim.x + threadIdx.x;   // 0..16383
    out[i] = g_U[i] / (g_S[i >> 8] + EPS);
}

// ---------------------------------------------------------------------------
extern "C" void kernel_launch(void* const* d_in, const int* in_sizes, int n_in,
                              void* d_out, int out_size) {
    const float* x    = (const float*)d_in[0];
    const float* W    = (const float*)d_in[1];
    const float* bias = (const float*)d_in[2];
    const float* uw   = (const float*)d_in[3];
    const int*   mask = (const int*)d_in[4];
    float* out = (float*)d_out;

    cudaFuncSetAttribute(gemm_fused_kernel,
                         cudaFuncAttributeMaxDynamicSharedMemorySize, SMEM_TOTAL);

    prep_kernel<<<256, 256>>>(W);

    gemm_fused_kernel<<<M_DIM / BM, 256, SMEM_TOTAL>>>(x, bias, uw, mask);

    norm_kernel<<<B_DIM * D_DIM / 256, 256>>>(out);
}

// round 12
// speedup vs baseline: 1.2190x; 1.1048x over previous
#include <cuda_runtime.h>
#include <cuda_fp16.h>
#include <math.h>
#include <stdint.h>

// ---------------- problem dims ----------------
#define B_DIM 64
#define T_DIM 2048
#define D_DIM 256
#define M_DIM (B_DIM * T_DIM)   // 131072
#define EPS 1e-7f
#define WSCALE 16.0f
#define WSCALE_INV 0.0625f

// ---------------- GEMM tiling ----------------
#define BM 64
#define BK 32
#define NIT (D_DIM / BK)        // 8 k-chunks
#define NSTAGE_B 3
#define SA_B 80                 // smem row stride bytes (32 halves + 16B pad)

#define A_CH_BYTES (BM * SA_B)               // 5120 per k-chunk
#define A_TOTAL (NIT * A_CH_BYTES)           // 40960 (persistent)
#define B_ST_BYTES (256 * SA_B)              // 20480 per stage
#define A_CH(c) ((c) * A_CH_BYTES)
#define B_ST(s) (A_TOTAL + (s) * B_ST_BYTES)
#define SMEM_TOTAL (A_TOTAL + NSTAGE_B * B_ST_BYTES)   // 102400

// ---------------- scratch globals ----------------
__device__ float g_U[B_DIM * D_DIM];   // unnormalized output
__device__ float g_S[B_DIM];           // exp sums
__device__ __align__(16) __half g_Wt[D_DIM * D_DIM];   // [n][k], W*16 fp16

// ---------------- helpers ----------------
__device__ __forceinline__ uint32_t smem_u32(const void* p) {
    uint32_t a;
    asm("{ .reg .u64 t; cvta.to.shared.u64 t, %1; cvt.u32.u64 %0, t; }"
        : "=r"(a) : "l"(p));
    return a;
}

__device__ __forceinline__ void mma16816(float* c, const uint32_t* a,
                                         uint32_t b0, uint32_t b1) {
    asm volatile(
        "mma.sync.aligned.m16n8k16.row.col.f32.f16.f16.f32 "
        "{%0,%1,%2,%3}, {%4,%5,%6,%7}, {%8,%9}, {%0,%1,%2,%3};\n"
        : "+f"(c[0]), "+f"(c[1]), "+f"(c[2]), "+f"(c[3])
        : "r"(a[0]), "r"(a[1]), "r"(a[2]), "r"(a[3]), "r"(b0), "r"(b1));
}

__device__ __forceinline__ void ldsm_x4(uint32_t* r, uint32_t addr) {
    asm volatile("ldmatrix.sync.aligned.m8n8.x4.shared.b16 {%0,%1,%2,%3}, [%4];"
        : "=r"(r[0]), "=r"(r[1]), "=r"(r[2]), "=r"(r[3]) : "r"(addr));
}

__device__ __forceinline__ void cp_async16(uint32_t dst, const void* src) {
    asm volatile("cp.async.cg.shared.global [%0], [%1], 16;"
                 :: "r"(dst), "l"(src));
}
#define CP_COMMIT() asm volatile("cp.async.commit_group;" ::: "memory")
#define CP_WAIT1()  asm volatile("cp.async.wait_group 1;" ::: "memory")

// ---------------------------------------------------------------------------
// Prep: zero g_U/g_S; transpose W*16 into fp16 [n][k].
// grid 128 x 128: each thread handles a float4 (4 W elements).
// ---------------------------------------------------------------------------
__global__ void prep_kernel(const float* __restrict__ W) {
    int idx = blockIdx.x * blockDim.x + threadIdx.x;   // 0..16383
    if (idx < B_DIM * D_DIM) g_U[idx] = 0.0f;
    if (idx < B_DIM) g_S[idx] = 0.0f;
    int k = idx >> 6;              // 0..255
    int n4 = (idx & 63) * 4;       // 0,4,..252
    float4 v = *(const float4*)&W[k * D_DIM + n4];
    g_Wt[(n4 + 0) * D_DIM + k] = __float2half_rn(v.x * WSCALE);
    g_Wt[(n4 + 1) * D_DIM + k] = __float2half_rn(v.y * WSCALE);
    g_Wt[(n4 + 2) * D_DIM + k] = __float2half_rn(v.z * WSCALE);
    g_Wt[(n4 + 3) * D_DIM + k] = __float2half_rn(v.w * WSCALE);
}

// ---------------------------------------------------------------------------
// Fused GEMM + tanh + uw-dot + exp + weighted-sum partials.
// grid = M/64 = 2048, block = 256 (8 warps: 2m x 4n), warp tile 32x64.
// A persistent in smem (fp16) but loaded PIPELINED (chunk c+1 staged during
// iteration c).  B via 3-stage cp.async ring.  2 CTAs/SM.
// ---------------------------------------------------------------------------
__global__ __launch_bounds__(256, 2) void gemm_fused_kernel(
    const float* __restrict__ x,      // [M, 256]
    const float* __restrict__ bias,   // [256]
    const float* __restrict__ uw,     // [256]
    const int*   __restrict__ mask)   // [M]
{
    extern __shared__ char smem[];
    __shared__ float red[BM];
    __shared__ float sm_e[BM];
    const uint32_t sb = smem_u32(smem);
    const int tid = threadIdx.x;
    const int wid = tid >> 5;
    const int lane = tid & 31;
    const int wm = wid >> 2;       // 0..1
    const int wn = wid & 3;        // 0..3
    const int gid = lane >> 2;     // 0..7
    const int tg = lane & 3;       // 0..3
    const int m0 = blockIdx.x * BM;

    float acc[2][8][4];
#pragma unroll
    for (int mt = 0; mt < 2; mt++)
#pragma unroll
        for (int nt = 0; nt < 8; nt++)
#pragma unroll
            for (int r = 0; r < 4; r++) acc[mt][nt][r] = 0.0f;

    // ---- load indexing ----
    const int ar = tid >> 2;             // x row 0..63
    const int ak8 = (tid & 3) * 8;       // x k-offset within chunk (8 floats)
    const int wr0 = tid >> 2;            // W base row (then +i*64)
    const int wq = tid & 3;              // W 16B slice index

    // ---- ldmatrix addressing ----
    const uint32_t a_lds = sb + (wm * 32 + (lane & 15)) * SA_B + (lane >> 4) * 16;
    const int brow = wn * 64 + (lane & 7) + ((lane >> 4) << 3);  // + p*16
    const int bkh = (lane >> 3) & 1;

    float4 pa0, pa1;

#define LDG_A(c)                                                              \
    do {                                                                      \
        int k0 = (c) * BK;                                                    \
        pa0 = *(const float4*)&x[(size_t)(m0 + ar) * D_DIM + k0 + ak8];       \
        pa1 = *(const float4*)&x[(size_t)(m0 + ar) * D_DIM + k0 + ak8 + 4];   \
    } while (0)

#define STS_A(c)                                                              \
    do {                                                                      \
        union { __half2 h[4]; uint4 u; } hh;                                  \
        hh.h[0] = __floats2half2_rn(pa0.x, pa0.y);                            \
        hh.h[1] = __floats2half2_rn(pa0.z, pa0.w);                            \
        hh.h[2] = __floats2half2_rn(pa1.x, pa1.y);                            \
        hh.h[3] = __floats2half2_rn(pa1.z, pa1.w);                            \
        *(uint4*)(smem + A_CH(c) + ar * SA_B + ak8 * 2) = hh.u;               \
    } while (0)

#define CPB(c, s)                                                             \
    do {                                                                      \
        int k0 = (c) * BK;                                                    \
        _Pragma("unroll")                                                     \
        for (int i = 0; i < 4; i++) {                                         \
            int row = wr0 + i * 64;                                           \
            int q = wq ^ ((row >> 3) & 3);                                    \
            cp_async16(sb + B_ST(s) + row * SA_B + q * 16,                    \
                       &g_Wt[row * D_DIM + k0 + wq * 8]);                     \
        }                                                                     \
    } while (0)

    // prologue: B0/B1 in flight, A0 staged, A1 in regs
    CPB(0, 0); CP_COMMIT();
    CPB(1, 1); CP_COMMIT();
    LDG_A(0);
    STS_A(0);
    LDG_A(1);

#pragma unroll
    for (int c = 0; c < NIT; c++) {
        const int cur = c % NSTAGE_B;
        CP_WAIT1();                            // B of chunk c landed
        __syncthreads();                       // + A STS visible
        if (c + 1 < NIT) STS_A(c + 1);         // persistent slot c+1
        if (c + 2 < NIT) {
            CPB(c + 2, (c + 2) % NSTAGE_B);
            LDG_A(c + 2);
        }
        CP_COMMIT();                           // exactly one group per iter

        uint32_t a[2][2][4];
#pragma unroll
        for (int mt = 0; mt < 2; mt++)
#pragma unroll
            for (int ks = 0; ks < 2; ks++)
                ldsm_x4(a[mt][ks], a_lds + A_CH(c) + mt * 16 * SA_B + ks * 32);

#pragma unroll
        for (int p = 0; p < 4; p++) {
            int row = brow + p * 16;
            int x3 = (row >> 3) & 3;
            uint32_t baddr = sb + B_ST(cur) + row * SA_B;
            uint32_t b0[4], b1[4];
            ldsm_x4(b0, baddr + ((bkh + 0) ^ x3) * 16);
            ldsm_x4(b1, baddr + ((bkh + 2) ^ x3) * 16);
#pragma unroll
            for (int mt = 0; mt < 2; mt++) {
                mma16816(acc[mt][2 * p],     a[mt][0], b0[0], b0[1]);
                mma16816(acc[mt][2 * p + 1], a[mt][0], b0[2], b0[3]);
                mma16816(acc[mt][2 * p],     a[mt][1], b1[0], b1[1]);
                mma16816(acc[mt][2 * p + 1], a[mt][1], b1[2], b1[3]);
            }
        }
    }

    // ---- epilogue 1: score(m) = sum_n tanh(acc/16 + b[n]) * uw[n] ----
    if (tid < BM) red[tid] = 0.0f;
    __syncthreads();

    float rowsum[4] = {0.f, 0.f, 0.f, 0.f};
#pragma unroll
    for (int nt = 0; nt < 8; nt++) {
        int c0 = wn * 64 + nt * 8 + tg * 2;
        float u0 = __ldg(&uw[c0]), u1 = __ldg(&uw[c0 + 1]);
        float b0 = __ldg(&bias[c0]), b1 = __ldg(&bias[c0 + 1]);
#pragma unroll
        for (int mt = 0; mt < 2; mt++) {
            rowsum[mt * 2 + 0] += tanhf(fmaf(acc[mt][nt][0], WSCALE_INV, b0)) * u0
                                + tanhf(fmaf(acc[mt][nt][1], WSCALE_INV, b1)) * u1;
            rowsum[mt * 2 + 1] += tanhf(fmaf(acc[mt][nt][2], WSCALE_INV, b0)) * u0
                                + tanhf(fmaf(acc[mt][nt][3], WSCALE_INV, b1)) * u1;
        }
    }
#pragma unroll
    for (int i = 0; i < 4; i++) {
        rowsum[i] += __shfl_xor_sync(0xffffffffu, rowsum[i], 1);
        rowsum[i] += __shfl_xor_sync(0xffffffffu, rowsum[i], 2);
    }
    if (tg == 0) {
        atomicAdd(&red[wm * 32 + gid], rowsum[0]);
        atomicAdd(&red[wm * 32 + gid + 8], rowsum[1]);
        atomicAdd(&red[wm * 32 + 16 + gid], rowsum[2]);
        atomicAdd(&red[wm * 32 + 16 + gid + 8], rowsum[3]);
    }
    __syncthreads();

    // ---- epilogue 2: e_t, S partial, U partial from persistent fp16 A ----
    const int b = m0 >> 11;   // 2048 rows per batch
    if (tid < BM) {
        float e = expf(red[tid]) * (float)mask[m0 + tid];
        sm_e[tid] = e;
#pragma unroll
        for (int off = 16; off > 0; off >>= 1)
            e += __shfl_xor_sync(0xffffffffu, e, off);
        if ((tid & 31) == 0) atomicAdd(&g_S[b], e);
    }
    __syncthreads();

    {
        const int d = tid;               // 0..255
        const int ch = d >> 5;           // k-chunk
        const int kk = d & 31;           // k within chunk
        const __half* col = (const __half*)(smem + A_CH(ch) + kk * 2);
        float u = 0.0f;
#pragma unroll 8
        for (int t = 0; t < BM; t++)
            u = fmaf(sm_e[t], __half2float(col[t * (SA_B / 2)]), u);
        atomicAdd(&g_U[b * D_DIM + d], u);
    }
}

// ---------------------------------------------------------------------------
// Normalize: out[b,d] = U[b,d] / (S[b] + EPS)
// ---------------------------------------------------------------------------
__global__ void norm_kernel(float* __restrict__ out) {
    int i = blockIdx.x * blockDim.x + threadIdx.x;   // 0..16383
    out[i] = g_U[i] / (g_S[i >> 8] + EPS);
}

// ---------------------------------------------------------------------------
extern "C" void kernel_launch(void* const* d_in, const int* in_sizes, int n_in,
                              void* d_out, int out_size) {
    const float* x    = (const float*)d_in[0];
    const float* W    = (const float*)d_in[1];
    const float* bias = (const float*)d_in[2];
    const float* uw   = (const float*)d_in[3];
    const int*   mask = (const int*)d_in[4];
    float* out = (float*)d_out;

    cudaFuncSetAttribute(gemm_fused_kernel,
                         cudaFuncAttributeMaxDynamicSharedMemorySize, SMEM_TOTAL);

    prep_kernel<<<128, 128>>>(W);

    gemm_fused_kernel<<<M_DIM / BM, 256, SMEM_TOTAL>>>(x, bias, uw, mask);

    norm_kernel<<<B_DIM * D_DIM / 256, 256>>>(out);
}

// round 13
// speedup vs baseline: 1.3374x; 1.0971x over previous
#include <cuda_runtime.h>
#include <cuda_fp16.h>
#include <math.h>
#include <stdint.h>

// ---------------- problem dims ----------------
#define B_DIM 64
#define T_DIM 2048
#define D_DIM 256
#define M_DIM (B_DIM * T_DIM)   // 131072
#define EPS 1e-7f
#define WSCALE 16.0f
#define WSCALE_INV 0.0625f

// ---------------- GEMM tiling ----------------
#define BM 64
#define BK 32
#define NIT (D_DIM / BK)        // 8 k-chunks
#define NSTAGE_B 3
#define SA_B 80                 // smem row stride bytes (32 halves + 16B pad)

#define A_CH_BYTES (BM * SA_B)               // 5120 per k-chunk
#define A_TOTAL (NIT * A_CH_BYTES)           // 40960 (persistent)
#define B_ST_BYTES (256 * SA_B)              // 20480 per stage
#define A_CH(c) ((c) * A_CH_BYTES)
#define B_ST(s) (A_TOTAL + (s) * B_ST_BYTES)
#define SMEM_TOTAL (A_TOTAL + NSTAGE_B * B_ST_BYTES)   // 102400

// ---------------- scratch globals ----------------
__device__ float g_U[B_DIM * D_DIM];   // unnormalized output
__device__ float g_S[B_DIM];           // exp sums
__device__ __align__(16) __half g_Wt[D_DIM * D_DIM];   // [n][k], W*16 fp16

// ---------------- helpers ----------------
__device__ __forceinline__ uint32_t smem_u32(const void* p) {
    uint32_t a;
    asm("{ .reg .u64 t; cvta.to.shared.u64 t, %1; cvt.u32.u64 %0, t; }"
        : "=r"(a) : "l"(p));
    return a;
}

__device__ __forceinline__ float tanh_fast(float x) {
    float y;
    asm("tanh.approx.f32 %0, %1;" : "=f"(y) : "f"(x));
    return y;
}

__device__ __forceinline__ void mma16816(float* c, const uint32_t* a,
                                         uint32_t b0, uint32_t b1) {
    asm volatile(
        "mma.sync.aligned.m16n8k16.row.col.f32.f16.f16.f32 "
        "{%0,%1,%2,%3}, {%4,%5,%6,%7}, {%8,%9}, {%0,%1,%2,%3};\n"
        : "+f"(c[0]), "+f"(c[1]), "+f"(c[2]), "+f"(c[3])
        : "r"(a[0]), "r"(a[1]), "r"(a[2]), "r"(a[3]), "r"(b0), "r"(b1));
}

__device__ __forceinline__ void ldsm_x4(uint32_t* r, uint32_t addr) {
    asm volatile("ldmatrix.sync.aligned.m8n8.x4.shared.b16 {%0,%1,%2,%3}, [%4];"
        : "=r"(r[0]), "=r"(r[1]), "=r"(r[2]), "=r"(r[3]) : "r"(addr));
}

__device__ __forceinline__ void cp_async16(uint32_t dst, const void* src) {
    asm volatile("cp.async.cg.shared.global [%0], [%1], 16;"
                 :: "r"(dst), "l"(src));
}
#define CP_COMMIT() asm volatile("cp.async.commit_group;" ::: "memory")
#define CP_WAIT1()  asm volatile("cp.async.wait_group 1;" ::: "memory")

// ---------------------------------------------------------------------------
// Prep: zero g_U/g_S; transpose W*16 into fp16 [n][k] via smem tiles.
// grid 16 (4x4 tiles of 64x64), block 256. Both sides coalesced.
// ---------------------------------------------------------------------------
__global__ void prep_kernel(const float* __restrict__ W) {
    __shared__ __half st[64][72];   // [k_local][n_local], padded
    const int kb = (blockIdx.x >> 2) * 64;
    const int nb = (blockIdx.x & 3) * 64;
    const int tid = threadIdx.x;

    // zero g_U (16 blocks * 256 threads * 4 floats = 16384) and g_S
    *(float4*)&g_U[(blockIdx.x * 256 + tid) * 4] = make_float4(0.f, 0.f, 0.f, 0.f);
    if (blockIdx.x == 0 && tid < B_DIM) g_S[tid] = 0.0f;

    // load 64x64 fp32 tile coalesced, convert, store to smem
    const int r = tid >> 4;              // 0..15
    const int c4 = (tid & 15) * 4;       // 0..60
#pragma unroll
    for (int i = 0; i < 4; i++) {
        int kl = r + i * 16;
        float4 v = *(const float4*)&W[(kb + kl) * D_DIM + nb + c4];
        st[kl][c4 + 0] = __float2half_rn(v.x * WSCALE);
        st[kl][c4 + 1] = __float2half_rn(v.y * WSCALE);
        st[kl][c4 + 2] = __float2half_rn(v.z * WSCALE);
        st[kl][c4 + 3] = __float2half_rn(v.w * WSCALE);
    }
    __syncthreads();

    // write transposed, coalesced 16B along k
    const int n = tid >> 2;              // 0..63
    const int kq = (tid & 3) * 16;       // 0,16,32,48
    union { __half h[16]; uint4 u[2]; } t;
#pragma unroll
    for (int j = 0; j < 16; j++) t.h[j] = st[kq + j][n];
    *(uint4*)&g_Wt[(nb + n) * D_DIM + kb + kq] = t.u[0];
    *(uint4*)&g_Wt[(nb + n) * D_DIM + kb + kq + 8] = t.u[1];
}

// ---------------------------------------------------------------------------
// Fused GEMM + tanh + uw-dot + exp + weighted-sum partials.
// grid = M/64 = 2048, block = 256 (8 warps: 2m x 4n), warp tile 32x64.
// A persistent in smem (fp16), pipelined load. B via 3-stage cp.async ring.
// 2 CTAs/SM.
// ---------------------------------------------------------------------------
__global__ __launch_bounds__(256, 2) void gemm_fused_kernel(
    const float* __restrict__ x,      // [M, 256]
    const float* __restrict__ bias,   // [256]
    const float* __restrict__ uw,     // [256]
    const int*   __restrict__ mask)   // [M]
{
    extern __shared__ char smem[];
    __shared__ float red[BM];
    __shared__ float sm_e[BM];
    const uint32_t sb = smem_u32(smem);
    const int tid = threadIdx.x;
    const int wid = tid >> 5;
    const int lane = tid & 31;
    const int wm = wid >> 2;       // 0..1
    const int wn = wid & 3;        // 0..3
    const int gid = lane >> 2;     // 0..7
    const int tg = lane & 3;       // 0..3
    const int m0 = blockIdx.x * BM;

    float acc[2][8][4];
#pragma unroll
    for (int mt = 0; mt < 2; mt++)
#pragma unroll
        for (int nt = 0; nt < 8; nt++)
#pragma unroll
            for (int r = 0; r < 4; r++) acc[mt][nt][r] = 0.0f;

    // ---- load indexing ----
    const int ar = tid >> 2;             // x row 0..63
    const int ak8 = (tid & 3) * 8;       // x k-offset within chunk (8 floats)
    const int wr0 = tid >> 2;            // W base row (then +i*64)
    const int wq = tid & 3;              // W 16B slice index

    // ---- ldmatrix addressing ----
    const uint32_t a_lds = sb + (wm * 32 + (lane & 15)) * SA_B + (lane >> 4) * 16;
    const int brow = wn * 64 + (lane & 7) + ((lane >> 4) << 3);  // + p*16
    const int bkh = (lane >> 3) & 1;

    float4 pa0, pa1;

#define LDG_A(c)                                                              \
    do {                                                                      \
        int k0 = (c) * BK;                                                    \
        pa0 = *(const float4*)&x[(size_t)(m0 + ar) * D_DIM + k0 + ak8];       \
        pa1 = *(const float4*)&x[(size_t)(m0 + ar) * D_DIM + k0 + ak8 + 4];   \
    } while (0)

#define STS_A(c)                                                              \
    do {                                                                      \
        union { __half2 h[4]; uint4 u; } hh;                                  \
        hh.h[0] = __floats2half2_rn(pa0.x, pa0.y);                            \
        hh.h[1] = __floats2half2_rn(pa0.z, pa0.w);                            \
        hh.h[2] = __floats2half2_rn(pa1.x, pa1.y);                            \
        hh.h[3] = __floats2half2_rn(pa1.z, pa1.w);                            \
        *(uint4*)(smem + A_CH(c) + ar * SA_B + ak8 * 2) = hh.u;               \
    } while (0)

#define CPB(c, s)                                                             \
    do {                                                                      \
        int k0 = (c) * BK;                                                    \
        _Pragma("unroll")                                                     \
        for (int i = 0; i < 4; i++) {                                         \
            int row = wr0 + i * 64;                                           \
            int q = wq ^ ((row >> 3) & 3);                                    \
            cp_async16(sb + B_ST(s) + row * SA_B + q * 16,                    \
                       &g_Wt[row * D_DIM + k0 + wq * 8]);                     \
        }                                                                     \
    } while (0)

    // prologue: B0/B1 in flight, A0 staged, A1 in regs
    CPB(0, 0); CP_COMMIT();
    CPB(1, 1); CP_COMMIT();
    LDG_A(0);
    STS_A(0);
    LDG_A(1);

#pragma unroll
    for (int c = 0; c < NIT; c++) {
        const int cur = c % NSTAGE_B;
        CP_WAIT1();                            // B of chunk c landed
        __syncthreads();                       // + A STS visible
        if (c + 1 < NIT) STS_A(c + 1);         // persistent slot c+1
        if (c + 2 < NIT) {
            CPB(c + 2, (c + 2) % NSTAGE_B);
            LDG_A(c + 2);
        }
        CP_COMMIT();                           // exactly one group per iter

        uint32_t a[2][2][4];
#pragma unroll
        for (int mt = 0; mt < 2; mt++)
#pragma unroll
            for (int ks = 0; ks < 2; ks++)
                ldsm_x4(a[mt][ks], a_lds + A_CH(c) + mt * 16 * SA_B + ks * 32);

#pragma unroll
        for (int p = 0; p < 4; p++) {
            int row = brow + p * 16;
            int x3 = (row >> 3) & 3;
            uint32_t baddr = sb + B_ST(cur) + row * SA_B;
            uint32_t b0[4], b1[4];
            ldsm_x4(b0, baddr + ((bkh + 0) ^ x3) * 16);
            ldsm_x4(b1, baddr + ((bkh + 2) ^ x3) * 16);
#pragma unroll
            for (int mt = 0; mt < 2; mt++) {
                mma16816(acc[mt][2 * p],     a[mt][0], b0[0], b0[1]);
                mma16816(acc[mt][2 * p + 1], a[mt][0], b0[2], b0[3]);
                mma16816(acc[mt][2 * p],     a[mt][1], b1[0], b1[1]);
                mma16816(acc[mt][2 * p + 1], a[mt][1], b1[2], b1[3]);
            }
        }
    }

    // ---- epilogue 1: score(m) = sum_n tanh(acc/16 + b[n]) * uw[n] ----
    if (tid < BM) red[tid] = 0.0f;
    __syncthreads();

    float rowsum[4] = {0.f, 0.f, 0.f, 0.f};
#pragma unroll
    for (int nt = 0; nt < 8; nt++) {
        int c0 = wn * 64 + nt * 8 + tg * 2;
        float u0 = __ldg(&uw[c0]), u1 = __ldg(&uw[c0 + 1]);
        float b0 = __ldg(&bias[c0]), b1 = __ldg(&bias[c0 + 1]);
#pragma unroll
        for (int mt = 0; mt < 2; mt++) {
            rowsum[mt * 2 + 0] += tanh_fast(fmaf(acc[mt][nt][0], WSCALE_INV, b0)) * u0
                                + tanh_fast(fmaf(acc[mt][nt][1], WSCALE_INV, b1)) * u1;
            rowsum[mt * 2 + 1] += tanh_fast(fmaf(acc[mt][nt][2], WSCALE_INV, b0)) * u0
                                + tanh_fast(fmaf(acc[mt][nt][3], WSCALE_INV, b1)) * u1;
        }
    }
#pragma unroll
    for (int i = 0; i < 4; i++) {
        rowsum[i] += __shfl_xor_sync(0xffffffffu, rowsum[i], 1);
        rowsum[i] += __shfl_xor_sync(0xffffffffu, rowsum[i], 2);
    }
    if (tg == 0) {
        atomicAdd(&red[wm * 32 + gid], rowsum[0]);
        atomicAdd(&red[wm * 32 + gid + 8], rowsum[1]);
        atomicAdd(&red[wm * 32 + 16 + gid], rowsum[2]);
        atomicAdd(&red[wm * 32 + 16 + gid + 8], rowsum[3]);
    }
    __syncthreads();

    // ---- epilogue 2: e_t, S partial, U partial from persistent fp16 A ----
    const int b = m0 >> 11;   // 2048 rows per batch
    if (tid < BM) {
        float e = expf(red[tid]) * (float)mask[m0 + tid];
        sm_e[tid] = e;
#pragma unroll
        for (int off = 16; off > 0; off >>= 1)
            e += __shfl_xor_sync(0xffffffffu, e, off);
        if ((tid & 31) == 0) atomicAdd(&g_S[b], e);
    }
    __syncthreads();

    {
        const int d = tid;               // 0..255
        const int ch = d >> 5;           // k-chunk
        const int kk = d & 31;           // k within chunk
        const __half* col = (const __half*)(smem + A_CH(ch) + kk * 2);
        float u = 0.0f;
#pragma unroll 8
        for (int t = 0; t < BM; t++)
            u = fmaf(sm_e[t], __half2float(col[t * (SA_B / 2)]), u);
        atomicAdd(&g_U[b * D_DIM + d], u);
    }
}

// ---------------------------------------------------------------------------
// Normalize: out[b,d] = U[b,d] / (S[b] + EPS)
// ---------------------------------------------------------------------------
__global__ void norm_kernel(float* __restrict__ out) {
    int i = blockIdx.x * blockDim.x + threadIdx.x;   // 0..16383
    out[i] = g_U[i] / (g_S[i >> 8] + EPS);
}

// ---------------------------------------------------------------------------
extern "C" void kernel_launch(void* const* d_in, const int* in_sizes, int n_in,
                              void* d_out, int out_size) {
    const float* x    = (const float*)d_in[0];
    const float* W    = (const float*)d_in[1];
    const float* bias = (const float*)d_in[2];
    const float* uw   = (const float*)d_in[3];
    const int*   mask = (const int*)d_in[4];
    float* out = (float*)d_out;

    cudaFuncSetAttribute(gemm_fused_kernel,
                         cudaFuncAttributeMaxDynamicSharedMemorySize, SMEM_TOTAL);

    prep_kernel<<<16, 256>>>(W);

    gemm_fused_kernel<<<M_DIM / BM, 256, SMEM_TOTAL>>>(x, bias, uw, mask);

    norm_kernel<<<B_DIM * D_DIM / 256, 256>>>(out);
}